// round 8
// baseline (speedup 1.0000x reference)
#include <cuda_runtime.h>
#include <cuda_fp16.h>
#include <cuda_fp8.h>
#include <cstdint>

#define BN 4
#define NN 4096
#define CC 256
#define DD 32
#define OUT_E (4*64*64*256)
#define PSCALE 4096.0f

// Scratch (device globals -> no allocations)
__device__ __half   g_qh [BN * NN * DD];
__device__ __half   g_kh [BN * NN * DD];
__device__ uint8_t  g_v8t[(long)BN * CC * NN];   // V transposed: [b][c][j], e4m3

// ---------------------------------------------------------------------------
// helpers
// ---------------------------------------------------------------------------
__device__ __forceinline__ uint32_t smem_u32(const void* p) {
    return (uint32_t)__cvta_generic_to_shared(p);
}
__device__ __forceinline__ void ldsm4(uint32_t* r, uint32_t addr) {
    asm volatile("ldmatrix.sync.aligned.m8n8.x4.shared.b16 {%0,%1,%2,%3}, [%4];"
                 : "=r"(r[0]), "=r"(r[1]), "=r"(r[2]), "=r"(r[3]) : "r"(addr));
}
__device__ __forceinline__ void mma_f16(float* c, const uint32_t* a,
                                        uint32_t b0, uint32_t b1) {
    asm volatile("mma.sync.aligned.m16n8k16.row.col.f32.f16.f16.f32 "
                 "{%0,%1,%2,%3}, {%4,%5,%6,%7}, {%8,%9}, {%0,%1,%2,%3};"
                 : "+f"(c[0]), "+f"(c[1]), "+f"(c[2]), "+f"(c[3])
                 : "r"(a[0]), "r"(a[1]), "r"(a[2]), "r"(a[3]), "r"(b0), "r"(b1));
}
__device__ __forceinline__ void mma_f8(float* c, const uint32_t* a,
                                       uint32_t b0, uint32_t b1) {
    asm volatile("mma.sync.aligned.m16n8k32.row.col.f32.e4m3.e4m3.f32 "
                 "{%0,%1,%2,%3}, {%4,%5,%6,%7}, {%8,%9}, {%0,%1,%2,%3};"
                 : "+f"(c[0]), "+f"(c[1]), "+f"(c[2]), "+f"(c[3])
                 : "r"(a[0]), "r"(a[1]), "r"(a[2]), "r"(a[3]), "r"(b0), "r"(b1));
}
__device__ __forceinline__ unsigned short f2_to_e4m3x2(float lo, float hi) {
    return (unsigned short)__nv_cvt_float2_to_fp8x2(make_float2(lo, hi),
                                                    __NV_SATFINITE, __NV_E4M3);
}
#define CP16(dst, src) \
    asm volatile("cp.async.cg.shared.global [%0], [%1], 16;" :: "r"(dst), "l"(src))
#define CP_COMMIT() asm volatile("cp.async.commit_group;" ::: "memory")
#define CP_WAIT(n)  asm volatile("cp.async.wait_group %0;" :: "n"(n) : "memory")

// smem layout (bytes). All tile rows stride 80B -> conflict-free ldmatrix.
#define Q_OFF     0        // 64 x 32 half             (5120)
#define P_OFF     5120     // 2 bufs x 64x64 e4m3      (10240)
#define K2_OFF    15360    // 4 stages x 64x32 half    (20480)
#define V_OFF     35840    // 3 stages x 256x64 e4m3   (61440); pass1 K1 here
#define SRED_OFF  97280    // 64 x 2 f32
#define SS_OFF    97792    // 64 f32
#define SMEM_ATTN 98048
#define K1_STAGE  20480    // 256 rows x 80B (fp16)
#define V_STAGE   20480    // 256 rows x 80B (fp8)
#define K2_STAGE  5120     // 64 rows x 80B (fp16)
#define P_BUF     5120

// ---------------------------------------------------------------------------
// Kernel 1: fused q,k,v projections. 64 rows per block.
// ---------------------------------------------------------------------------
__global__ void __launch_bounds__(256, 2) qkv_kernel(
    const float* __restrict__ x,
    const float* __restrict__ Wq, const float* __restrict__ bq,
    const float* __restrict__ Wk, const float* __restrict__ bk,
    const float* __restrict__ Wv, const float* __restrict__ bv)
{
    int row0 = blockIdx.x * 64;
    int tid  = threadIdx.x;
    int lane = tid & 31, warp = tid >> 5;

    __shared__ __align__(16) float xs[64][36];
    __shared__ __align__(16) float wq[32][36];
    __shared__ __align__(16) float wk[32][36];
    __shared__ __align__(16) float wv[32][260];

    float av_[8][8], aq[8], ak[8];
#pragma unroll
    for (int r = 0; r < 8; r++) {
        aq[r] = 0.f; ak[r] = 0.f;
#pragma unroll
        for (int c = 0; c < 8; c++) av_[r][c] = 0.f;
    }

    for (int kc = 0; kc < CC; kc += 32) {
        __syncthreads();
#pragma unroll
        for (int rr = 0; rr < 8; rr++) {
            int r = warp * 8 + rr;
            xs[r][lane] = x[(long)(row0 + r) * CC + kc + lane];
        }
        {
            int kk = tid >> 3, d4 = tid & 7;
            *(float4*)&wq[kk][d4 * 4] = *(const float4*)&Wq[(kc + kk) * DD + d4 * 4];
            *(float4*)&wk[kk][d4 * 4] = *(const float4*)&Wk[(kc + kk) * DD + d4 * 4];
        }
#pragma unroll
        for (int p = 0; p < 8; p++) {
            int idx = tid + p * 256;
            int r = idx >> 6, c4 = idx & 63;
            *(float4*)&wv[r][c4 * 4] = *(const float4*)&Wv[(long)(kc + r) * CC + c4 * 4];
        }
        __syncthreads();
#pragma unroll
        for (int k4 = 0; k4 < 8; k4++) {
            float4 a4[8];
#pragma unroll
            for (int r = 0; r < 8; r++)
                a4[r] = *(const float4*)&xs[warp * 8 + r][k4 * 4];
#pragma unroll
            for (int qq = 0; qq < 4; qq++) {
                int kk = k4 * 4 + qq;
                float bvq = wq[kk][lane];
                float bvk = wk[kk][lane];
                float bvv[8];
                *(float4*)&bvv[0] = *(const float4*)&wv[kk][lane * 4];
                *(float4*)&bvv[4] = *(const float4*)&wv[kk][128 + lane * 4];
#pragma unroll
                for (int r = 0; r < 8; r++) {
                    float xv = ((const float*)&a4[r])[qq];
                    aq[r] += xv * bvq;
                    ak[r] += xv * bvk;
#pragma unroll
                    for (int c = 0; c < 8; c++)
                        av_[r][c] += xv * bvv[c];
                }
            }
        }
    }
    float bbq = bq[lane], bbk = bk[lane];
#pragma unroll
    for (int r = 0; r < 8; r++) {
        long o = (long)(row0 + warp * 8 + r) * DD + lane;
        g_qh[o] = __float2half_rn(aq[r] + bbq);
        g_kh[o] = __float2half_rn(ak[r] + bbk);
    }
    int rowg = row0 + warp * 8;
    int bb   = rowg / NN;
    int jj   = rowg % NN;
    uint8_t* vt = g_v8t + (long)bb * CC * NN;
#pragma unroll
    for (int h = 0; h < 2; h++) {
#pragma unroll
        for (int cc = 0; cc < 4; cc++) {
            int c = h * 128 + lane * 4 + cc;
            float bias = bv[c];
            int idx = h * 4 + cc;
            uint32_t lo = (uint32_t)f2_to_e4m3x2(av_[0][idx] + bias, av_[1][idx] + bias)
                        | ((uint32_t)f2_to_e4m3x2(av_[2][idx] + bias, av_[3][idx] + bias) << 16);
            uint32_t hi = (uint32_t)f2_to_e4m3x2(av_[4][idx] + bias, av_[5][idx] + bias)
                        | ((uint32_t)f2_to_e4m3x2(av_[6][idx] + bias, av_[7][idx] + bias) << 16);
            *(uint2*)&vt[(long)c * NN + jj] = make_uint2(lo, hi);
        }
    }
}

// ---------------------------------------------------------------------------
// Kernel 2: fused attention, software-pipelined pass 2 (one sync per iter).
//  iter t: E(t)->exp->P(buf t&1)+att(t)  AND  AV(t-1) from P(buf (t-1)&1)
// ---------------------------------------------------------------------------
__global__ void __launch_bounds__(256, 2) attn_kernel(
    const float* __restrict__ x, const float* __restrict__ gamma,
    float* __restrict__ att_out, float* __restrict__ y)
{
    extern __shared__ __align__(16) char smem[];
    const uint32_t sb = smem_u32(smem);
    const int tid  = threadIdx.x;
    const int lane = tid & 31, w = tid >> 5;
    const int wi = w & 3, wj = w >> 2;
    const int avi = w & 1, avc = w >> 1;

    const int b  = blockIdx.y;
    const int i0 = blockIdx.x * 64;

    const __half*  qg  = g_qh + ((long)b * NN + i0) * DD;
    const __half*  kg  = g_kh + (long)b * NN * DD;
    const uint8_t* vtg = g_v8t + (long)b * CC * NN;

    // ---- Q tile -> smem ----
    {
        int r = tid >> 2, ch = tid & 3;
        *(uint4*)(smem + Q_OFF + r * 80 + ch * 16) =
            *(const uint4*)(qg + r * DD + ch * 8);
    }
    // prefetch K1 stage 0 (256 rows x 64B)
    {
        uint32_t kst = sb + V_OFF;
#pragma unroll
        for (int p = 0; p < 4; p++) {
            int idx = tid + p * 256;
            int r = idx >> 2, ch = idx & 3;
            CP16(kst + r * 80 + ch * 16, kg + r * DD + ch * 8);
        }
        CP_COMMIT();
    }
    __syncthreads();

    // ---- preload Q fragments (held all kernel) ----
    uint32_t qf[2][4];
    {
        uint32_t base = sb + Q_OFF
            + (wi * 16 + (lane & 7) + ((lane >> 3) & 1) * 8) * 80
            + (lane >> 4) * 16;
        ldsm4(qf[0], base);
        ldsm4(qf[1], base + 32);
    }

    // =========================== PASS 1 (JT=256) ============================
    float s0 = 0.f, s1 = 0.f;
    for (int t = 0; t < 16; t++) {
        if (t + 1 < 16) {
            uint32_t kst = sb + V_OFF + ((t + 1) % 3) * K1_STAGE;
            const __half* src = kg + (t + 1) * 256 * DD;
#pragma unroll
            for (int p = 0; p < 4; p++) {
                int idx = tid + p * 256;
                int r = idx >> 2, ch = idx & 3;
                CP16(kst + r * 80 + ch * 16, src + r * DD + ch * 8);
            }
        }
        CP_COMMIT();
        CP_WAIT(1);
        __syncthreads();

        uint32_t kst = sb + V_OFF + (t % 3) * K1_STAGE;
        uint32_t bbase = kst + (wj * 128 + (lane & 7)) * 80 + (lane >> 3) * 16;
#pragma unroll
        for (int nt = 0; nt < 16; nt++) {
            uint32_t bf[4];
            ldsm4(bf, bbase + nt * 8 * 80);
            float c[4] = {0.f, 0.f, 0.f, 0.f};
            mma_f16(c, qf[0], bf[0], bf[1]);
            mma_f16(c, qf[1], bf[2], bf[3]);
            s0 += __expf(c[0]) + __expf(c[1]);
            s1 += __expf(c[2]) + __expf(c[3]);
        }
        // no trailing sync: next iter's prefetch targets a stage no live warp reads
    }
    s0 += __shfl_xor_sync(0xffffffffu, s0, 1);
    s0 += __shfl_xor_sync(0xffffffffu, s0, 2);
    s1 += __shfl_xor_sync(0xffffffffu, s1, 1);
    s1 += __shfl_xor_sync(0xffffffffu, s1, 2);
    {
        float* sred = (float*)(smem + SRED_OFF);
        if ((lane & 3) == 0) {
            int r = wi * 16 + (lane >> 2);
            sred[r * 2 + wj]       = s0;
            sred[(r + 8) * 2 + wj] = s1;
        }
    }
    __syncthreads();
    if (tid < 64) {
        float* sred = (float*)(smem + SRED_OFF);
        ((float*)(smem + SS_OFF))[tid] = 1.0f / (sred[tid * 2] + sred[tid * 2 + 1]);
    }
    __syncthreads();
    const float is0 = ((const float*)(smem + SS_OFF))[wi * 16 + (lane >> 2)];
    const float is1 = ((const float*)(smem + SS_OFF))[wi * 16 + (lane >> 2) + 8];

    // ---- pass2 prolog prefetch: C_a = {V(0), K2(0)}, C_b = {K2(1)} ----
    {
        uint32_t vst = sb + V_OFF;
#pragma unroll
        for (int p = 0; p < 4; p++) {
            int idx = tid + p * 256;
            int c = idx >> 2, ch = idx & 3;
            CP16(vst + c * 80 + ch * 16, vtg + (long)c * NN + ch * 16);
        }
        int r = tid >> 2, ch = tid & 3;
        CP16(sb + K2_OFF + r * 80 + ch * 16, kg + r * DD + ch * 8);
        CP_COMMIT();
        CP16(sb + K2_OFF + K2_STAGE + r * 80 + ch * 16, kg + (64 + r) * DD + ch * 8);
        CP_COMMIT();
    }

    // =========================== PASS 2 (pipelined) ========================
    float acc[2][8][4];
#pragma unroll
    for (int mt = 0; mt < 2; mt++)
#pragma unroll
        for (int nt = 0; nt < 8; nt++)
#pragma unroll
            for (int u = 0; u < 4; u++) acc[mt][nt][u] = 0.f;

    float* ab = att_out ? att_out + ((long)b * NN + i0) * NN : (float*)0;
    const int er0 = wi * 16 + (lane >> 2);
    int vs_r = 0;   // V read stage for AV(t-1): (t-1)%3
    int vs_w = 1;   // V write stage for V(t+1): (t+1)%3

    for (int t = 0; t <= 64; t++) {
        CP_WAIT(1);
        __syncthreads();

        // ---- E(t) -> exp -> P(buf t&1) + att(t) ----
        if (t < 64) {
            const int j0 = t * 64;
            uint32_t k2t = sb + K2_OFF + (t & 3) * K2_STAGE;
            uint32_t ebase = k2t + (wj * 32 + (lane & 7)) * 80 + (lane >> 3) * 16;
            const int pw = P_OFF + (t & 1) * P_BUF;
#pragma unroll
            for (int nt = 0; nt < 4; nt++) {
                uint32_t bf[4];
                ldsm4(bf, ebase + nt * 8 * 80);
                float c[4] = {0.f, 0.f, 0.f, 0.f};
                mma_f16(c, qf[0], bf[0], bf[1]);
                mma_f16(c, qf[1], bf[2], bf[3]);
                float a0 = __expf(c[0]) * is0, a1 = __expf(c[1]) * is0;
                float a2 = __expf(c[2]) * is1, a3 = __expf(c[3]) * is1;
                int col = wj * 32 + nt * 8 + ((lane & 3) << 1);
                *(unsigned short*)(smem + pw + er0 * 80 + col) =
                    f2_to_e4m3x2(a0 * PSCALE, a1 * PSCALE);
                *(unsigned short*)(smem + pw + (er0 + 8) * 80 + col) =
                    f2_to_e4m3x2(a2 * PSCALE, a3 * PSCALE);
                if (ab) {
                    *(float2*)&ab[(long)er0 * NN + j0 + col]       = make_float2(a0, a1);
                    *(float2*)&ab[(long)(er0 + 8) * NN + j0 + col] = make_float2(a2, a3);
                }
            }
        }

        // ---- AV(t-1): O += P'((t-1)&1) @ V^T(stage (t-1)%3) ----
        if (t > 0) {
            uint32_t vst = sb + V_OFF + vs_r * V_STAGE;
            uint32_t pA  = sb + P_OFF + ((t - 1) & 1) * P_BUF
                + (avi * 32 + (lane & 7) + ((lane >> 3) & 1) * 8) * 80
                + ((lane >> 4) & 1) * 16;
            uint32_t af[2][2][4];
#pragma unroll
            for (int mt = 0; mt < 2; mt++) {
                ldsm4(af[mt][0], pA + mt * 16 * 80);
                ldsm4(af[mt][1], pA + mt * 16 * 80 + 32);
            }
#pragma unroll
            for (int kk = 0; kk < 2; kk++) {
#pragma unroll
                for (int ntg = 0; ntg < 4; ntg++) {
                    uint32_t bv[4];
                    uint32_t baddr = vst
                        + (avc * 64 + ntg * 16 + (lane & 7) + ((lane >> 4) & 1) * 8) * 80
                        + ((lane >> 3) & 1) * 16 + kk * 32;
                    ldsm4(bv, baddr);
                    mma_f8(acc[0][ntg * 2],     af[0][kk], bv[0], bv[1]);
                    mma_f8(acc[0][ntg * 2 + 1], af[0][kk], bv[2], bv[3]);
                    mma_f8(acc[1][ntg * 2],     af[1][kk], bv[0], bv[1]);
                    mma_f8(acc[1][ntg * 2 + 1], af[1][kk], bv[2], bv[3]);
                }
            }
            vs_r = (vs_r == 2) ? 0 : vs_r + 1;
        }

        // ---- end-of-iter prefetch: V(t+1), K2(t+2) ----
        if (t <= 62) {
            uint32_t vst = sb + V_OFF + vs_w * V_STAGE;
            const uint8_t* vsrc = vtg + (t + 1) * 64;
#pragma unroll
            for (int p = 0; p < 4; p++) {
                int idx = tid + p * 256;
                int c = idx >> 2, ch = idx & 3;
                CP16(vst + c * 80 + ch * 16, vsrc + (long)c * NN + ch * 16);
            }
            vs_w = (vs_w == 2) ? 0 : vs_w + 1;
        }
        if (t <= 61) {
            uint32_t k2t = sb + K2_OFF + ((t + 2) & 3) * K2_STAGE;
            const __half* ksrc = kg + (t + 2) * 64 * DD;
            int r = tid >> 2, ch = tid & 3;
            CP16(k2t + r * 80 + ch * 16, ksrc + r * DD + ch * 8);
        }
        CP_COMMIT();
    }

    // ---- epilogue: y = acc*(gamma/PSCALE) + x ----
    const float g = gamma[0] * (1.0f / PSCALE);
    const float* xb = x + ((long)b * NN + i0) * CC;
    float* yb = y + ((long)b * NN + i0) * CC;
#pragma unroll
    for (int mt = 0; mt < 2; mt++) {
        int r0 = avi * 32 + mt * 16 + (lane >> 2);
#pragma unroll
        for (int nt = 0; nt < 8; nt++) {
            int c = avc * 64 + nt * 8 + ((lane & 3) << 1);
            float2 x0 = *(const float2*)&xb[(long)r0 * CC + c];
            float2 x1 = *(const float2*)&xb[(long)(r0 + 8) * CC + c];
            float2 o0, o1;
            o0.x = acc[mt][nt][0] * g + x0.x;  o0.y = acc[mt][nt][1] * g + x0.y;
            o1.x = acc[mt][nt][2] * g + x1.x;  o1.y = acc[mt][nt][3] * g + x1.y;
            *(float2*)&yb[(long)r0 * CC + c]       = o0;
            *(float2*)&yb[(long)(r0 + 8) * CC + c] = o1;
        }
    }
}

// ---------------------------------------------------------------------------
extern "C" void kernel_launch(void* const* d_in, const int* in_sizes, int n_in,
                              void* d_out, int out_size)
{
    const float* x     = (const float*)d_in[0];
    const float* Wq    = (const float*)d_in[1];
    const float* bq    = (const float*)d_in[2];
    const float* Wk    = (const float*)d_in[3];
    const float* bk    = (const float*)d_in[4];
    const float* Wv    = (const float*)d_in[5];
    const float* bv    = (const float*)d_in[6];
    const float* gamma = (const float*)d_in[7];
    float* y = (float*)d_out;

    const long ATT_E = (long)BN * NN * NN;
    float* att_out = 0;
    if ((long)out_size == (long)OUT_E + ATT_E) att_out = y + OUT_E;

    cudaFuncSetAttribute(attn_kernel, cudaFuncAttributeMaxDynamicSharedMemorySize,
                         SMEM_ATTN);

    qkv_kernel<<<BN * NN / 64, 256>>>(x, Wq, bq, Wk, bk, Wv, bv);
    attn_kernel<<<dim3(NN / 64, BN), 256, SMEM_ATTN>>>(x, gamma, att_out, y);
}

// round 9
// speedup vs baseline: 1.1925x; 1.1925x over previous
#include <cuda_runtime.h>
#include <cuda_fp16.h>
#include <cuda_fp8.h>
#include <cstdint>

#define BN 4
#define NN 4096
#define CC 256
#define DD 32
#define OUT_E (4*64*64*256)
#define PSCALE 4096.0f

// Scratch (device globals -> no allocations)
__device__ __half   g_qh [BN * NN * DD];
__device__ __half   g_kh [BN * NN * DD];
__device__ uint8_t  g_v8t[(long)BN * CC * NN];   // V transposed: [b][c][j], e4m3

// ---------------------------------------------------------------------------
// helpers
// ---------------------------------------------------------------------------
__device__ __forceinline__ uint32_t smem_u32(const void* p) {
    return (uint32_t)__cvta_generic_to_shared(p);
}
__device__ __forceinline__ void ldsm4(uint32_t* r, uint32_t addr) {
    asm volatile("ldmatrix.sync.aligned.m8n8.x4.shared.b16 {%0,%1,%2,%3}, [%4];"
                 : "=r"(r[0]), "=r"(r[1]), "=r"(r[2]), "=r"(r[3]) : "r"(addr));
}
__device__ __forceinline__ void mma_f16(float* c, const uint32_t* a,
                                        uint32_t b0, uint32_t b1) {
    asm volatile("mma.sync.aligned.m16n8k16.row.col.f32.f16.f16.f32 "
                 "{%0,%1,%2,%3}, {%4,%5,%6,%7}, {%8,%9}, {%0,%1,%2,%3};"
                 : "+f"(c[0]), "+f"(c[1]), "+f"(c[2]), "+f"(c[3])
                 : "r"(a[0]), "r"(a[1]), "r"(a[2]), "r"(a[3]), "r"(b0), "r"(b1));
}
__device__ __forceinline__ void mma_f8(float* c, const uint32_t* a,
                                       uint32_t b0, uint32_t b1) {
    asm volatile("mma.sync.aligned.m16n8k32.row.col.f32.e4m3.e4m3.f32 "
                 "{%0,%1,%2,%3}, {%4,%5,%6,%7}, {%8,%9}, {%0,%1,%2,%3};"
                 : "+f"(c[0]), "+f"(c[1]), "+f"(c[2]), "+f"(c[3])
                 : "r"(a[0]), "r"(a[1]), "r"(a[2]), "r"(a[3]), "r"(b0), "r"(b1));
}
__device__ __forceinline__ unsigned short f2_to_e4m3x2(float lo, float hi) {
    return (unsigned short)__nv_cvt_float2_to_fp8x2(make_float2(lo, hi),
                                                    __NV_SATFINITE, __NV_E4M3);
}
#define CP16(dst, src) \
    asm volatile("cp.async.cg.shared.global [%0], [%1], 16;" :: "r"(dst), "l"(src))
#define CP_COMMIT() asm volatile("cp.async.commit_group;" ::: "memory")
#define CP_WAIT(n)  asm volatile("cp.async.wait_group %0;" :: "n"(n) : "memory")

// attn smem layout (bytes). All tile rows stride 80B -> conflict-free ldmatrix.
#define Q_OFF     0
#define P_OFF     5120
#define K2_OFF    15360
#define V_OFF     35840
#define SRED_OFF  97280
#define SS_OFF    97792
#define SMEM_ATTN 98048
#define K1_STAGE  20480
#define V_STAGE   20480
#define K2_STAGE  5120
#define P_BUF     5120

// ---------------------------------------------------------------------------
// Kernel 1: q = x@Wq + bq, k = x@Wk + bk -> fp16   (FFMA, small: 0.27 GFMA)
// ---------------------------------------------------------------------------
__global__ void __launch_bounds__(256) qkf_kernel(
    const float* __restrict__ x,
    const float* __restrict__ Wq, const float* __restrict__ bq,
    const float* __restrict__ Wk, const float* __restrict__ bk)
{
    int row0 = blockIdx.x * 64;
    int tid  = threadIdx.x;
    int lane = tid & 31;
    int rg   = tid >> 5;

    __shared__ __align__(16) float xs[64][68];
    __shared__ float wsq[64][33];
    __shared__ float wsk[64][33];

    float aq[8], ak[8];
#pragma unroll
    for (int r = 0; r < 8; r++) { aq[r] = 0.f; ak[r] = 0.f; }

    for (int kc = 0; kc < CC; kc += 64) {
        __syncthreads();
#pragma unroll
        for (int p = 0; p < 16; p++) {
            int idx = tid + p * 256;
            int r = idx >> 6, kk = idx & 63;
            xs[r][kk] = x[(long)(row0 + r) * CC + kc + kk];
        }
#pragma unroll
        for (int p = 0; p < 8; p++) {
            int idx = tid + p * 256;
            int kk = idx >> 5, d = idx & 31;
            wsq[kk][d] = Wq[(kc + kk) * DD + d];
            wsk[kk][d] = Wk[(kc + kk) * DD + d];
        }
        __syncthreads();
#pragma unroll
        for (int k4 = 0; k4 < 16; k4++) {
            float4 a4[8];
#pragma unroll
            for (int r = 0; r < 8; r++)
                a4[r] = *(const float4*)&xs[rg * 8 + r][k4 * 4];
#pragma unroll
            for (int qq = 0; qq < 4; qq++) {
                float bvq = wsq[k4 * 4 + qq][lane];
                float bvk = wsk[k4 * 4 + qq][lane];
#pragma unroll
                for (int r = 0; r < 8; r++) {
                    float av = ((const float*)&a4[r])[qq];
                    aq[r] += av * bvq;
                    ak[r] += av * bvk;
                }
            }
        }
    }
    float bbq = bq[lane], bbk = bk[lane];
#pragma unroll
    for (int r = 0; r < 8; r++) {
        long o = (long)(row0 + rg * 8 + r) * DD + lane;
        g_qh[o] = __float2half_rn(aq[r] + bbq);
        g_kh[o] = __float2half_rn(ak[r] + bbk);
    }
}

// ---------------------------------------------------------------------------
// Kernel 2: v = x@Wv + bv via fp16 HMMA -> transposed e4m3 g_v8t[b][c][j]
//  64 rows x 256 cols per block, 8 warps (2m x 4n), K chunks of 32.
//  smem: X tile 64x32 fp16 (stride 80), W^T tile 256x32 fp16 (stride 80);
//        after mma, W region is reused as the u8 transpose-bounce tile.
// ---------------------------------------------------------------------------
#define VK_X_OFF 0        // 64 * 80  = 5120
#define VK_W_OFF 5120     // 256 * 80 = 20480
#define VK_T_OFF 5120     // aliases W after last mma
__global__ void __launch_bounds__(256, 2) v16_kernel(
    const float* __restrict__ x,
    const float* __restrict__ Wv, const float* __restrict__ bv)
{
    __shared__ __align__(16) char sm[25600];
    const uint32_t sb = smem_u32(sm);
    int row0 = blockIdx.x * 64;
    int tid  = threadIdx.x;
    int lane = tid & 31, warp = tid >> 5;
    int wm = warp & 1, wn = warp >> 1;

    float acc[2][8][4];
#pragma unroll
    for (int mt = 0; mt < 2; mt++)
#pragma unroll
        for (int nt = 0; nt < 8; nt++)
#pragma unroll
            for (int u = 0; u < 4; u++) acc[mt][nt][u] = 0.f;

    for (int kc = 0; kc < CC; kc += 32) {
        __syncthreads();
        // x fp32 -> fp16 smem tile [64 rows][32 k], stride 80B
        {
            int r = tid >> 2, kq = (tid & 3) * 8;
            float4 xa = *(const float4*)&x[(long)(row0 + r) * CC + kc + kq];
            float4 xb = *(const float4*)&x[(long)(row0 + r) * CC + kc + kq + 4];
            __half2 h[4];
            h[0] = __floats2half2_rn(xa.x, xa.y);
            h[1] = __floats2half2_rn(xa.z, xa.w);
            h[2] = __floats2half2_rn(xb.x, xb.y);
            h[3] = __floats2half2_rn(xb.z, xb.w);
            *(uint4*)(sm + VK_X_OFF + r * 80 + kq * 2) = *(uint4*)h;
        }
        // W fp32 -> fp16 smem transposed: wt[n][kk], stride 80B
#pragma unroll
        for (int p = 0; p < 32; p++) {
            int kk = p, n = tid;
            float wv_ = Wv[(long)(kc + kk) * CC + n];
            *(__half*)(sm + VK_W_OFF + n * 80 + kk * 2) = __float2half_rn(wv_);
        }
        __syncthreads();

        // A fragments: 2 m-tiles x 2 k-halves
        uint32_t af[2][2][4];
#pragma unroll
        for (int mt = 0; mt < 2; mt++) {
            uint32_t abase = sb + VK_X_OFF
                + (wm * 32 + mt * 16 + (lane & 7) + ((lane >> 3) & 1) * 8) * 80
                + (lane >> 4) * 16;
            ldsm4(af[mt][0], abase);
            ldsm4(af[mt][1], abase + 32);
        }
#pragma unroll
        for (int nt = 0; nt < 8; nt++) {
            uint32_t bf[4];
            uint32_t bbase = sb + VK_W_OFF
                + (wn * 64 + nt * 8 + (lane & 7)) * 80 + (lane >> 3) * 16;
            ldsm4(bf, bbase);
            mma_f16(acc[0][nt], af[0][0], bf[0], bf[1]);
            mma_f16(acc[0][nt], af[0][1], bf[2], bf[3]);
            mma_f16(acc[1][nt], af[1][0], bf[0], bf[1]);
            mma_f16(acc[1][nt], af[1][1], bf[2], bf[3]);
        }
    }
    __syncthreads();   // all mma ldsm done -> W region reusable as T

    // quantize + bias -> u8 bounce tile T[c][j], stride 80B (j = local row)
    uint8_t* t8 = (uint8_t*)(sm + VK_T_OFF);
#pragma unroll
    for (int mt = 0; mt < 2; mt++) {
        int r = wm * 32 + mt * 16 + (lane >> 2);
#pragma unroll
        for (int nt = 0; nt < 8; nt++) {
            int c = wn * 64 + nt * 8 + ((lane & 3) << 1);
            float b0 = bv[c], b1 = bv[c + 1];
            unsigned short pa = f2_to_e4m3x2(acc[mt][nt][0] + b0, acc[mt][nt][1] + b1);
            unsigned short pb = f2_to_e4m3x2(acc[mt][nt][2] + b0, acc[mt][nt][3] + b1);
            t8[c * 80 + r]           = (uint8_t)(pa & 0xff);
            t8[(c + 1) * 80 + r]     = (uint8_t)(pa >> 8);
            t8[c * 80 + r + 8]       = (uint8_t)(pb & 0xff);
            t8[(c + 1) * 80 + r + 8] = (uint8_t)(pb >> 8);
        }
    }
    __syncthreads();

    // coalesced store: vt[c][jj + 0..63], 16B per thread-op
    int bb = row0 / NN;
    int jj = row0 % NN;
    uint8_t* vt = g_v8t + (long)bb * CC * NN;
#pragma unroll
    for (int p = 0; p < 4; p++) {
        int e = tid + p * 256;
        int c = e >> 2, j16 = (e & 3) * 16;
        uint4 v4 = *(uint4*)(sm + VK_T_OFF + c * 80 + j16);
        *(uint4*)&vt[(long)c * NN + jj + j16] = v4;
    }
}

// ---------------------------------------------------------------------------
// Kernel 3: fused attention (unchanged from R8; pipelined pass 2)
// ---------------------------------------------------------------------------
__global__ void __launch_bounds__(256, 2) attn_kernel(
    const float* __restrict__ x, const float* __restrict__ gamma,
    float* __restrict__ att_out, float* __restrict__ y)
{
    extern __shared__ __align__(16) char smem[];
    const uint32_t sb = smem_u32(smem);
    const int tid  = threadIdx.x;
    const int lane = tid & 31, w = tid >> 5;
    const int wi = w & 3, wj = w >> 2;
    const int avi = w & 1, avc = w >> 1;

    const int b  = blockIdx.y;
    const int i0 = blockIdx.x * 64;

    const __half*  qg  = g_qh + ((long)b * NN + i0) * DD;
    const __half*  kg  = g_kh + (long)b * NN * DD;
    const uint8_t* vtg = g_v8t + (long)b * CC * NN;

    {
        int r = tid >> 2, ch = tid & 3;
        *(uint4*)(smem + Q_OFF + r * 80 + ch * 16) =
            *(const uint4*)(qg + r * DD + ch * 8);
    }
    {
        uint32_t kst = sb + V_OFF;
#pragma unroll
        for (int p = 0; p < 4; p++) {
            int idx = tid + p * 256;
            int r = idx >> 2, ch = idx & 3;
            CP16(kst + r * 80 + ch * 16, kg + r * DD + ch * 8);
        }
        CP_COMMIT();
    }
    __syncthreads();

    uint32_t qf[2][4];
    {
        uint32_t base = sb + Q_OFF
            + (wi * 16 + (lane & 7) + ((lane >> 3) & 1) * 8) * 80
            + (lane >> 4) * 16;
        ldsm4(qf[0], base);
        ldsm4(qf[1], base + 32);
    }

    // =========================== PASS 1 (JT=256) ============================
    float s0 = 0.f, s1 = 0.f;
    for (int t = 0; t < 16; t++) {
        if (t + 1 < 16) {
            uint32_t kst = sb + V_OFF + ((t + 1) % 3) * K1_STAGE;
            const __half* src = kg + (t + 1) * 256 * DD;
#pragma unroll
            for (int p = 0; p < 4; p++) {
                int idx = tid + p * 256;
                int r = idx >> 2, ch = idx & 3;
                CP16(kst + r * 80 + ch * 16, src + r * DD + ch * 8);
            }
        }
        CP_COMMIT();
        CP_WAIT(1);
        __syncthreads();

        uint32_t kst = sb + V_OFF + (t % 3) * K1_STAGE;
        uint32_t bbase = kst + (wj * 128 + (lane & 7)) * 80 + (lane >> 3) * 16;
#pragma unroll
        for (int nt = 0; nt < 16; nt++) {
            uint32_t bf[4];
            ldsm4(bf, bbase + nt * 8 * 80);
            float c[4] = {0.f, 0.f, 0.f, 0.f};
            mma_f16(c, qf[0], bf[0], bf[1]);
            mma_f16(c, qf[1], bf[2], bf[3]);
            s0 += __expf(c[0]) + __expf(c[1]);
            s1 += __expf(c[2]) + __expf(c[3]);
        }
    }
    s0 += __shfl_xor_sync(0xffffffffu, s0, 1);
    s0 += __shfl_xor_sync(0xffffffffu, s0, 2);
    s1 += __shfl_xor_sync(0xffffffffu, s1, 1);
    s1 += __shfl_xor_sync(0xffffffffu, s1, 2);
    {
        float* sred = (float*)(smem + SRED_OFF);
        if ((lane & 3) == 0) {
            int r = wi * 16 + (lane >> 2);
            sred[r * 2 + wj]       = s0;
            sred[(r + 8) * 2 + wj] = s1;
        }
    }
    __syncthreads();
    if (tid < 64) {
        float* sred = (float*)(smem + SRED_OFF);
        ((float*)(smem + SS_OFF))[tid] = 1.0f / (sred[tid * 2] + sred[tid * 2 + 1]);
    }
    __syncthreads();
    const float is0 = ((const float*)(smem + SS_OFF))[wi * 16 + (lane >> 2)];
    const float is1 = ((const float*)(smem + SS_OFF))[wi * 16 + (lane >> 2) + 8];

    {
        uint32_t vst = sb + V_OFF;
#pragma unroll
        for (int p = 0; p < 4; p++) {
            int idx = tid + p * 256;
            int c = idx >> 2, ch = idx & 3;
            CP16(vst + c * 80 + ch * 16, vtg + (long)c * NN + ch * 16);
        }
        int r = tid >> 2, ch = tid & 3;
        CP16(sb + K2_OFF + r * 80 + ch * 16, kg + r * DD + ch * 8);
        CP_COMMIT();
        CP16(sb + K2_OFF + K2_STAGE + r * 80 + ch * 16, kg + (64 + r) * DD + ch * 8);
        CP_COMMIT();
    }

    // =========================== PASS 2 (pipelined) ========================
    float acc[2][8][4];
#pragma unroll
    for (int mt = 0; mt < 2; mt++)
#pragma unroll
        for (int nt = 0; nt < 8; nt++)
#pragma unroll
            for (int u = 0; u < 4; u++) acc[mt][nt][u] = 0.f;

    float* ab = att_out ? att_out + ((long)b * NN + i0) * NN : (float*)0;
    const int er0 = wi * 16 + (lane >> 2);
    int vs_r = 0;
    int vs_w = 1;

    for (int t = 0; t <= 64; t++) {
        CP_WAIT(1);
        __syncthreads();

        if (t < 64) {
            const int j0 = t * 64;
            uint32_t k2t = sb + K2_OFF + (t & 3) * K2_STAGE;
            uint32_t ebase = k2t + (wj * 32 + (lane & 7)) * 80 + (lane >> 3) * 16;
            const int pw = P_OFF + (t & 1) * P_BUF;
#pragma unroll
            for (int nt = 0; nt < 4; nt++) {
                uint32_t bf[4];
                ldsm4(bf, ebase + nt * 8 * 80);
                float c[4] = {0.f, 0.f, 0.f, 0.f};
                mma_f16(c, qf[0], bf[0], bf[1]);
                mma_f16(c, qf[1], bf[2], bf[3]);
                float a0 = __expf(c[0]) * is0, a1 = __expf(c[1]) * is0;
                float a2 = __expf(c[2]) * is1, a3 = __expf(c[3]) * is1;
                int col = wj * 32 + nt * 8 + ((lane & 3) << 1);
                *(unsigned short*)(smem + pw + er0 * 80 + col) =
                    f2_to_e4m3x2(a0 * PSCALE, a1 * PSCALE);
                *(unsigned short*)(smem + pw + (er0 + 8) * 80 + col) =
                    f2_to_e4m3x2(a2 * PSCALE, a3 * PSCALE);
                if (ab) {
                    *(float2*)&ab[(long)er0 * NN + j0 + col]       = make_float2(a0, a1);
                    *(float2*)&ab[(long)(er0 + 8) * NN + j0 + col] = make_float2(a2, a3);
                }
            }
        }

        if (t > 0) {
            uint32_t vst = sb + V_OFF + vs_r * V_STAGE;
            uint32_t pA  = sb + P_OFF + ((t - 1) & 1) * P_BUF
                + (avi * 32 + (lane & 7) + ((lane >> 3) & 1) * 8) * 80
                + ((lane >> 4) & 1) * 16;
            uint32_t af[2][2][4];
#pragma unroll
            for (int mt = 0; mt < 2; mt++) {
                ldsm4(af[mt][0], pA + mt * 16 * 80);
                ldsm4(af[mt][1], pA + mt * 16 * 80 + 32);
            }
#pragma unroll
            for (int kk = 0; kk < 2; kk++) {
#pragma unroll
                for (int ntg = 0; ntg < 4; ntg++) {
                    uint32_t bv[4];
                    uint32_t baddr = vst
                        + (avc * 64 + ntg * 16 + (lane & 7) + ((lane >> 4) & 1) * 8) * 80
                        + ((lane >> 3) & 1) * 16 + kk * 32;
                    ldsm4(bv, baddr);
                    mma_f8(acc[0][ntg * 2],     af[0][kk], bv[0], bv[1]);
                    mma_f8(acc[0][ntg * 2 + 1], af[0][kk], bv[2], bv[3]);
                    mma_f8(acc[1][ntg * 2],     af[1][kk], bv[0], bv[1]);
                    mma_f8(acc[1][ntg * 2 + 1], af[1][kk], bv[2], bv[3]);
                }
            }
            vs_r = (vs_r == 2) ? 0 : vs_r + 1;
        }

        if (t <= 62) {
            uint32_t vst = sb + V_OFF + vs_w * V_STAGE;
            const uint8_t* vsrc = vtg + (t + 1) * 64;
#pragma unroll
            for (int p = 0; p < 4; p++) {
                int idx = tid + p * 256;
                int c = idx >> 2, ch = idx & 3;
                CP16(vst + c * 80 + ch * 16, vsrc + (long)c * NN + ch * 16);
            }
            vs_w = (vs_w == 2) ? 0 : vs_w + 1;
        }
        if (t <= 61) {
            uint32_t k2t = sb + K2_OFF + ((t + 2) & 3) * K2_STAGE;
            const __half* ksrc = kg + (t + 2) * 64 * DD;
            int r = tid >> 2, ch = tid & 3;
            CP16(k2t + r * 80 + ch * 16, ksrc + r * DD + ch * 8);
        }
        CP_COMMIT();
    }

    // ---- epilogue: y = acc*(gamma/PSCALE) + x ----
    const float g = gamma[0] * (1.0f / PSCALE);
    const float* xb = x + ((long)b * NN + i0) * CC;
    float* yb = y + ((long)b * NN + i0) * CC;
#pragma unroll
    for (int mt = 0; mt < 2; mt++) {
        int r0 = avi * 32 + mt * 16 + (lane >> 2);
#pragma unroll
        for (int nt = 0; nt < 8; nt++) {
            int c = avc * 64 + nt * 8 + ((lane & 3) << 1);
            float2 x0 = *(const float2*)&xb[(long)r0 * CC + c];
            float2 x1 = *(const float2*)&xb[(long)(r0 + 8) * CC + c];
            float2 o0, o1;
            o0.x = acc[mt][nt][0] * g + x0.x;  o0.y = acc[mt][nt][1] * g + x0.y;
            o1.x = acc[mt][nt][2] * g + x1.x;  o1.y = acc[mt][nt][3] * g + x1.y;
            *(float2*)&yb[(long)r0 * CC + c]       = o0;
            *(float2*)&yb[(long)(r0 + 8) * CC + c] = o1;
        }
    }
}

// ---------------------------------------------------------------------------
extern "C" void kernel_launch(void* const* d_in, const int* in_sizes, int n_in,
                              void* d_out, int out_size)
{
    const float* x     = (const float*)d_in[0];
    const float* Wq    = (const float*)d_in[1];
    const float* bq    = (const float*)d_in[2];
    const float* Wk    = (const float*)d_in[3];
    const float* bk    = (const float*)d_in[4];
    const float* Wv    = (const float*)d_in[5];
    const float* bv    = (const float*)d_in[6];
    const float* gamma = (const float*)d_in[7];
    float* y = (float*)d_out;

    const long ATT_E = (long)BN * NN * NN;
    float* att_out = 0;
    if ((long)out_size == (long)OUT_E + ATT_E) att_out = y + OUT_E;

    cudaFuncSetAttribute(attn_kernel, cudaFuncAttributeMaxDynamicSharedMemorySize,
                         SMEM_ATTN);

    qkf_kernel<<<BN * NN / 64, 256>>>(x, Wq, bq, Wk, bk);
    v16_kernel<<<BN * NN / 64, 256>>>(x, Wv, bv);
    attn_kernel<<<dim3(NN / 64, BN), 256, SMEM_ATTN>>>(x, gamma, att_out, y);
}

// round 10
// speedup vs baseline: 1.2429x; 1.0423x over previous
#include <cuda_runtime.h>
#include <cuda_fp16.h>
#include <cuda_fp8.h>
#include <cstdint>

#define BN 4
#define NN 4096
#define CC 256
#define DD 32
#define OUT_E (4*64*64*256)
#define PSCALE 4096.0f

// Scratch (device globals -> no allocations)
__device__ __half   g_qh [BN * NN * DD];
__device__ __half   g_kh [BN * NN * DD];
__device__ uint8_t  g_v8t[(long)BN * CC * NN];   // V transposed: [b][c][j], e4m3

// ---------------------------------------------------------------------------
// helpers
// ---------------------------------------------------------------------------
__device__ __forceinline__ uint32_t smem_u32(const void* p) {
    return (uint32_t)__cvta_generic_to_shared(p);
}
__device__ __forceinline__ void ldsm4(uint32_t* r, uint32_t addr) {
    asm volatile("ldmatrix.sync.aligned.m8n8.x4.shared.b16 {%0,%1,%2,%3}, [%4];"
                 : "=r"(r[0]), "=r"(r[1]), "=r"(r[2]), "=r"(r[3]) : "r"(addr));
}
__device__ __forceinline__ void mma_f16(float* c, const uint32_t* a,
                                        uint32_t b0, uint32_t b1) {
    asm volatile("mma.sync.aligned.m16n8k16.row.col.f32.f16.f16.f32 "
                 "{%0,%1,%2,%3}, {%4,%5,%6,%7}, {%8,%9}, {%0,%1,%2,%3};"
                 : "+f"(c[0]), "+f"(c[1]), "+f"(c[2]), "+f"(c[3])
                 : "r"(a[0]), "r"(a[1]), "r"(a[2]), "r"(a[3]), "r"(b0), "r"(b1));
}
__device__ __forceinline__ void mma_f8(float* c, const uint32_t* a,
                                       uint32_t b0, uint32_t b1) {
    asm volatile("mma.sync.aligned.m16n8k32.row.col.f32.e4m3.e4m3.f32 "
                 "{%0,%1,%2,%3}, {%4,%5,%6,%7}, {%8,%9}, {%0,%1,%2,%3};"
                 : "+f"(c[0]), "+f"(c[1]), "+f"(c[2]), "+f"(c[3])
                 : "r"(a[0]), "r"(a[1]), "r"(a[2]), "r"(a[3]), "r"(b0), "r"(b1));
}
__device__ __forceinline__ unsigned short f2_to_e4m3x2(float lo, float hi) {
    return (unsigned short)__nv_cvt_float2_to_fp8x2(make_float2(lo, hi),
                                                    __NV_SATFINITE, __NV_E4M3);
}
#define CP16(dst, src) \
    asm volatile("cp.async.cg.shared.global [%0], [%1], 16;" :: "r"(dst), "l"(src))
#define CP_COMMIT() asm volatile("cp.async.commit_group;" ::: "memory")
#define CP_WAIT(n)  asm volatile("cp.async.wait_group %0;" :: "n"(n) : "memory")

// attn smem layout (bytes). All tile rows stride 80B -> conflict-free ldmatrix.
#define Q_OFF     0
#define P_OFF     5120
#define K2_OFF    15360
#define V_OFF     35840
#define SRED_OFF  97280
#define SS_OFF    97792
#define SMEM_ATTN 98048
#define K1_STAGE  20480
#define V_STAGE   20480
#define K2_STAGE  5120
#define P_BUF     5120

// ---------------------------------------------------------------------------
// Kernel 1: fused q,k,v projections via fp16 HMMA.
//  v  -> transposed e4m3 g_v8t[b][c][j]
//  q,k -> fp16 g_qh/g_kh ([Wq|Wk] stacked as one N=64 GEMM sharing A-frags)
//  64 rows per block, 8 warps (2m x 4n), K chunks of 32.
// ---------------------------------------------------------------------------
#define VK_X_OFF   0        // 64 * 80   = 5120
#define VK_W_OFF   5120     // 256 * 80  = 20480
#define VK_QK_OFF  25600    // 64 * 80   = 5120   ([Wq|Wk]^T tile)
#define VK_T_OFF   5120     // aliases W after last mma
__global__ void __launch_bounds__(256, 2) qkv16_kernel(
    const float* __restrict__ x,
    const float* __restrict__ Wq, const float* __restrict__ bq,
    const float* __restrict__ Wk, const float* __restrict__ bk,
    const float* __restrict__ Wv, const float* __restrict__ bv)
{
    __shared__ __align__(16) char sm[30720];
    const uint32_t sb = smem_u32(sm);
    int row0 = blockIdx.x * 64;
    int tid  = threadIdx.x;
    int lane = tid & 31, warp = tid >> 5;
    int wm = warp & 1, wn = warp >> 1;

    float acc[2][8][4];      // V accumulators
    float aqk[2][2][4];      // q|k accumulators (16 cols per warp)
#pragma unroll
    for (int mt = 0; mt < 2; mt++) {
#pragma unroll
        for (int nt = 0; nt < 8; nt++)
#pragma unroll
            for (int u = 0; u < 4; u++) acc[mt][nt][u] = 0.f;
#pragma unroll
        for (int nt = 0; nt < 2; nt++)
#pragma unroll
            for (int u = 0; u < 4; u++) aqk[mt][nt][u] = 0.f;
    }

    for (int kc = 0; kc < CC; kc += 32) {
        __syncthreads();
        // x fp32 -> fp16 smem tile [64 rows][32 k], stride 80B
        {
            int r = tid >> 2, kq = (tid & 3) * 8;
            float4 xa = *(const float4*)&x[(long)(row0 + r) * CC + kc + kq];
            float4 xb = *(const float4*)&x[(long)(row0 + r) * CC + kc + kq + 4];
            __half2 h[4];
            h[0] = __floats2half2_rn(xa.x, xa.y);
            h[1] = __floats2half2_rn(xa.z, xa.w);
            h[2] = __floats2half2_rn(xb.x, xb.y);
            h[3] = __floats2half2_rn(xb.z, xb.w);
            *(uint4*)(sm + VK_X_OFF + r * 80 + kq * 2) = *(uint4*)h;
        }
        // Wv fp32 -> fp16 smem transposed: wt[n][kk], stride 80B
#pragma unroll
        for (int p = 0; p < 32; p++) {
            int kk = p, n = tid;
            float wv_ = Wv[(long)(kc + kk) * CC + n];
            *(__half*)(sm + VK_W_OFF + n * 80 + kk * 2) = __float2half_rn(wv_);
        }
        // [Wq|Wk] fp32 -> fp16 transposed: wqk[n][kk], n<32 = q, n>=32 = k
        {
            int n = tid & 63, kb = (tid >> 6) * 8;
#pragma unroll
            for (int k2 = 0; k2 < 8; k2++) {
                int kk = kb + k2;
                float wv_ = (n < 32) ? Wq[(long)(kc + kk) * DD + n]
                                     : Wk[(long)(kc + kk) * DD + (n - 32)];
                *(__half*)(sm + VK_QK_OFF + n * 80 + kk * 2) = __float2half_rn(wv_);
            }
        }
        __syncthreads();

        // A fragments: 2 m-tiles x 2 k-halves
        uint32_t af[2][2][4];
#pragma unroll
        for (int mt = 0; mt < 2; mt++) {
            uint32_t abase = sb + VK_X_OFF
                + (wm * 32 + mt * 16 + (lane & 7) + ((lane >> 3) & 1) * 8) * 80
                + (lane >> 4) * 16;
            ldsm4(af[mt][0], abase);
            ldsm4(af[mt][1], abase + 32);
        }
        // V GEMM
#pragma unroll
        for (int nt = 0; nt < 8; nt++) {
            uint32_t bf[4];
            uint32_t bbase = sb + VK_W_OFF
                + (wn * 64 + nt * 8 + (lane & 7)) * 80 + (lane >> 3) * 16;
            ldsm4(bf, bbase);
            mma_f16(acc[0][nt], af[0][0], bf[0], bf[1]);
            mma_f16(acc[0][nt], af[0][1], bf[2], bf[3]);
            mma_f16(acc[1][nt], af[1][0], bf[0], bf[1]);
            mma_f16(acc[1][nt], af[1][1], bf[2], bf[3]);
        }
        // q|k GEMM (16 cols per warp)
#pragma unroll
        for (int nt = 0; nt < 2; nt++) {
            uint32_t bf[4];
            uint32_t bbase = sb + VK_QK_OFF
                + (wn * 16 + nt * 8 + (lane & 7)) * 80 + (lane >> 3) * 16;
            ldsm4(bf, bbase);
            mma_f16(aqk[0][nt], af[0][0], bf[0], bf[1]);
            mma_f16(aqk[0][nt], af[0][1], bf[2], bf[3]);
            mma_f16(aqk[1][nt], af[1][0], bf[0], bf[1]);
            mma_f16(aqk[1][nt], af[1][1], bf[2], bf[3]);
        }
    }

    // ---- q/k epilogue: fp16 stores ----
#pragma unroll
    for (int mt = 0; mt < 2; mt++) {
#pragma unroll
        for (int nt = 0; nt < 2; nt++) {
            int r = wm * 32 + mt * 16 + (lane >> 2);
            int gcol = wn * 16 + nt * 8 + ((lane & 3) << 1);
            int isq = gcol < 32;
            int cc = isq ? gcol : gcol - 32;
            const float* bb_ = isq ? bq : bk;
            __half* dst = isq ? g_qh : g_kh;
            float b0 = bb_[cc], b1 = bb_[cc + 1];
            *(__half2*)&dst[(long)(row0 + r) * DD + cc] =
                __floats2half2_rn(aqk[mt][nt][0] + b0, aqk[mt][nt][1] + b1);
            *(__half2*)&dst[(long)(row0 + r + 8) * DD + cc] =
                __floats2half2_rn(aqk[mt][nt][2] + b0, aqk[mt][nt][3] + b1);
        }
    }

    __syncthreads();   // all mma ldsm done -> W region reusable as T

    // quantize + bias -> u8 bounce tile T[c][j], stride 80B (j = local row)
    uint8_t* t8 = (uint8_t*)(sm + VK_T_OFF);
#pragma unroll
    for (int mt = 0; mt < 2; mt++) {
        int r = wm * 32 + mt * 16 + (lane >> 2);
#pragma unroll
        for (int nt = 0; nt < 8; nt++) {
            int c = wn * 64 + nt * 8 + ((lane & 3) << 1);
            float b0 = bv[c], b1 = bv[c + 1];
            unsigned short pa = f2_to_e4m3x2(acc[mt][nt][0] + b0, acc[mt][nt][1] + b1);
            unsigned short pb = f2_to_e4m3x2(acc[mt][nt][2] + b0, acc[mt][nt][3] + b1);
            t8[c * 80 + r]           = (uint8_t)(pa & 0xff);
            t8[(c + 1) * 80 + r]     = (uint8_t)(pa >> 8);
            t8[c * 80 + r + 8]       = (uint8_t)(pb & 0xff);
            t8[(c + 1) * 80 + r + 8] = (uint8_t)(pb >> 8);
        }
    }
    __syncthreads();

    // coalesced store: vt[c][jj + 0..63], 16B per thread-op
    int bb = row0 / NN;
    int jj = row0 % NN;
    uint8_t* vt = g_v8t + (long)bb * CC * NN;
#pragma unroll
    for (int p = 0; p < 4; p++) {
        int e = tid + p * 256;
        int c = e >> 2, j16 = (e & 3) * 16;
        uint4 v4 = *(uint4*)(sm + VK_T_OFF + c * 80 + j16);
        *(uint4*)&vt[(long)c * NN + jj + j16] = v4;
    }
}

// ---------------------------------------------------------------------------
// Kernel 2: fused attention (unchanged from R9)
// ---------------------------------------------------------------------------
__global__ void __launch_bounds__(256, 2) attn_kernel(
    const float* __restrict__ x, const float* __restrict__ gamma,
    float* __restrict__ att_out, float* __restrict__ y)
{
    extern __shared__ __align__(16) char smem[];
    const uint32_t sb = smem_u32(smem);
    const int tid  = threadIdx.x;
    const int lane = tid & 31, w = tid >> 5;
    const int wi = w & 3, wj = w >> 2;
    const int avi = w & 1, avc = w >> 1;

    const int b  = blockIdx.y;
    const int i0 = blockIdx.x * 64;

    const __half*  qg  = g_qh + ((long)b * NN + i0) * DD;
    const __half*  kg  = g_kh + (long)b * NN * DD;
    const uint8_t* vtg = g_v8t + (long)b * CC * NN;

    {
        int r = tid >> 2, ch = tid & 3;
        *(uint4*)(smem + Q_OFF + r * 80 + ch * 16) =
            *(const uint4*)(qg + r * DD + ch * 8);
    }
    {
        uint32_t kst = sb + V_OFF;
#pragma unroll
        for (int p = 0; p < 4; p++) {
            int idx = tid + p * 256;
            int r = idx >> 2, ch = idx & 3;
            CP16(kst + r * 80 + ch * 16, kg + r * DD + ch * 8);
        }
        CP_COMMIT();
    }
    __syncthreads();

    uint32_t qf[2][4];
    {
        uint32_t base = sb + Q_OFF
            + (wi * 16 + (lane & 7) + ((lane >> 3) & 1) * 8) * 80
            + (lane >> 4) * 16;
        ldsm4(qf[0], base);
        ldsm4(qf[1], base + 32);
    }

    // =========================== PASS 1 (JT=256) ============================
    float s0 = 0.f, s1 = 0.f;
    for (int t = 0; t < 16; t++) {
        if (t + 1 < 16) {
            uint32_t kst = sb + V_OFF + ((t + 1) % 3) * K1_STAGE;
            const __half* src = kg + (t + 1) * 256 * DD;
#pragma unroll
            for (int p = 0; p < 4; p++) {
                int idx = tid + p * 256;
                int r = idx >> 2, ch = idx & 3;
                CP16(kst + r * 80 + ch * 16, src + r * DD + ch * 8);
            }
        }
        CP_COMMIT();
        CP_WAIT(1);
        __syncthreads();

        uint32_t kst = sb + V_OFF + (t % 3) * K1_STAGE;
        uint32_t bbase = kst + (wj * 128 + (lane & 7)) * 80 + (lane >> 3) * 16;
#pragma unroll
        for (int nt = 0; nt < 16; nt++) {
            uint32_t bf[4];
            ldsm4(bf, bbase + nt * 8 * 80);
            float c[4] = {0.f, 0.f, 0.f, 0.f};
            mma_f16(c, qf[0], bf[0], bf[1]);
            mma_f16(c, qf[1], bf[2], bf[3]);
            s0 += __expf(c[0]) + __expf(c[1]);
            s1 += __expf(c[2]) + __expf(c[3]);
        }
    }
    s0 += __shfl_xor_sync(0xffffffffu, s0, 1);
    s0 += __shfl_xor_sync(0xffffffffu, s0, 2);
    s1 += __shfl_xor_sync(0xffffffffu, s1, 1);
    s1 += __shfl_xor_sync(0xffffffffu, s1, 2);
    {
        float* sred = (float*)(smem + SRED_OFF);
        if ((lane & 3) == 0) {
            int r = wi * 16 + (lane >> 2);
            sred[r * 2 + wj]       = s0;
            sred[(r + 8) * 2 + wj] = s1;
        }
    }
    __syncthreads();
    if (tid < 64) {
        float* sred = (float*)(smem + SRED_OFF);
        ((float*)(smem + SS_OFF))[tid] = 1.0f / (sred[tid * 2] + sred[tid * 2 + 1]);
    }
    __syncthreads();
    const float is0 = ((const float*)(smem + SS_OFF))[wi * 16 + (lane >> 2)];
    const float is1 = ((const float*)(smem + SS_OFF))[wi * 16 + (lane >> 2) + 8];

    {
        uint32_t vst = sb + V_OFF;
#pragma unroll
        for (int p = 0; p < 4; p++) {
            int idx = tid + p * 256;
            int c = idx >> 2, ch = idx & 3;
            CP16(vst + c * 80 + ch * 16, vtg + (long)c * NN + ch * 16);
        }
        int r = tid >> 2, ch = tid & 3;
        CP16(sb + K2_OFF + r * 80 + ch * 16, kg + r * DD + ch * 8);
        CP_COMMIT();
        CP16(sb + K2_OFF + K2_STAGE + r * 80 + ch * 16, kg + (64 + r) * DD + ch * 8);
        CP_COMMIT();
    }

    // =========================== PASS 2 (pipelined) ========================
    float acc[2][8][4];
#pragma unroll
    for (int mt = 0; mt < 2; mt++)
#pragma unroll
        for (int nt = 0; nt < 8; nt++)
#pragma unroll
            for (int u = 0; u < 4; u++) acc[mt][nt][u] = 0.f;

    float* ab = att_out ? att_out + ((long)b * NN + i0) * NN : (float*)0;
    const int er0 = wi * 16 + (lane >> 2);
    int vs_r = 0;
    int vs_w = 1;

    for (int t = 0; t <= 64; t++) {
        CP_WAIT(1);
        __syncthreads();

        if (t < 64) {
            const int j0 = t * 64;
            uint32_t k2t = sb + K2_OFF + (t & 3) * K2_STAGE;
            uint32_t ebase = k2t + (wj * 32 + (lane & 7)) * 80 + (lane >> 3) * 16;
            const int pw = P_OFF + (t & 1) * P_BUF;
#pragma unroll
            for (int nt = 0; nt < 4; nt++) {
                uint32_t bf[4];
                ldsm4(bf, ebase + nt * 8 * 80);
                float c[4] = {0.f, 0.f, 0.f, 0.f};
                mma_f16(c, qf[0], bf[0], bf[1]);
                mma_f16(c, qf[1], bf[2], bf[3]);
                float a0 = __expf(c[0]) * is0, a1 = __expf(c[1]) * is0;
                float a2 = __expf(c[2]) * is1, a3 = __expf(c[3]) * is1;
                int col = wj * 32 + nt * 8 + ((lane & 3) << 1);
                *(unsigned short*)(smem + pw + er0 * 80 + col) =
                    f2_to_e4m3x2(a0 * PSCALE, a1 * PSCALE);
                *(unsigned short*)(smem + pw + (er0 + 8) * 80 + col) =
                    f2_to_e4m3x2(a2 * PSCALE, a3 * PSCALE);
                if (ab) {
                    *(float2*)&ab[(long)er0 * NN + j0 + col]       = make_float2(a0, a1);
                    *(float2*)&ab[(long)(er0 + 8) * NN + j0 + col] = make_float2(a2, a3);
                }
            }
        }

        if (t > 0) {
            uint32_t vst = sb + V_OFF + vs_r * V_STAGE;
            uint32_t pA  = sb + P_OFF + ((t - 1) & 1) * P_BUF
                + (avi * 32 + (lane & 7) + ((lane >> 3) & 1) * 8) * 80
                + ((lane >> 4) & 1) * 16;
            uint32_t af[2][2][4];
#pragma unroll
            for (int mt = 0; mt < 2; mt++) {
                ldsm4(af[mt][0], pA + mt * 16 * 80);
                ldsm4(af[mt][1], pA + mt * 16 * 80 + 32);
            }
#pragma unroll
            for (int kk = 0; kk < 2; kk++) {
#pragma unroll
                for (int ntg = 0; ntg < 4; ntg++) {
                    uint32_t bv[4];
                    uint32_t baddr = vst
                        + (avc * 64 + ntg * 16 + (lane & 7) + ((lane >> 4) & 1) * 8) * 80
                        + ((lane >> 3) & 1) * 16 + kk * 32;
                    ldsm4(bv, baddr);
                    mma_f8(acc[0][ntg * 2],     af[0][kk], bv[0], bv[1]);
                    mma_f8(acc[0][ntg * 2 + 1], af[0][kk], bv[2], bv[3]);
                    mma_f8(acc[1][ntg * 2],     af[1][kk], bv[0], bv[1]);
                    mma_f8(acc[1][ntg * 2 + 1], af[1][kk], bv[2], bv[3]);
                }
            }
            vs_r = (vs_r == 2) ? 0 : vs_r + 1;
        }

        if (t <= 62) {
            uint32_t vst = sb + V_OFF + vs_w * V_STAGE;
            const uint8_t* vsrc = vtg + (t + 1) * 64;
#pragma unroll
            for (int p = 0; p < 4; p++) {
                int idx = tid + p * 256;
                int c = idx >> 2, ch = idx & 3;
                CP16(vst + c * 80 + ch * 16, vsrc + (long)c * NN + ch * 16);
            }
            vs_w = (vs_w == 2) ? 0 : vs_w + 1;
        }
        if (t <= 61) {
            uint32_t k2t = sb + K2_OFF + ((t + 2) & 3) * K2_STAGE;
            const __half* ksrc = kg + (t + 2) * 64 * DD;
            int r = tid >> 2, ch = tid & 3;
            CP16(k2t + r * 80 + ch * 16, ksrc + r * DD + ch * 8);
        }
        CP_COMMIT();
    }

    // ---- epilogue: y = acc*(gamma/PSCALE) + x ----
    const float g = gamma[0] * (1.0f / PSCALE);
    const float* xb = x + ((long)b * NN + i0) * CC;
    float* yb = y + ((long)b * NN + i0) * CC;
#pragma unroll
    for (int mt = 0; mt < 2; mt++) {
        int r0 = avi * 32 + mt * 16 + (lane >> 2);
#pragma unroll
        for (int nt = 0; nt < 8; nt++) {
            int c = avc * 64 + nt * 8 + ((lane & 3) << 1);
            float2 x0 = *(const float2*)&xb[(long)r0 * CC + c];
            float2 x1 = *(const float2*)&xb[(long)(r0 + 8) * CC + c];
            float2 o0, o1;
            o0.x = acc[mt][nt][0] * g + x0.x;  o0.y = acc[mt][nt][1] * g + x0.y;
            o1.x = acc[mt][nt][2] * g + x1.x;  o1.y = acc[mt][nt][3] * g + x1.y;
            *(float2*)&yb[(long)r0 * CC + c]       = o0;
            *(float2*)&yb[(long)(r0 + 8) * CC + c] = o1;
        }
    }
}

// ---------------------------------------------------------------------------
extern "C" void kernel_launch(void* const* d_in, const int* in_sizes, int n_in,
                              void* d_out, int out_size)
{
    const float* x     = (const float*)d_in[0];
    const float* Wq    = (const float*)d_in[1];
    const float* bq    = (const float*)d_in[2];
    const float* Wk    = (const float*)d_in[3];
    const float* bk    = (const float*)d_in[4];
    const float* Wv    = (const float*)d_in[5];
    const float* bv    = (const float*)d_in[6];
    const float* gamma = (const float*)d_in[7];
    float* y = (float*)d_out;

    const long ATT_E = (long)BN * NN * NN;
    float* att_out = 0;
    if ((long)out_size == (long)OUT_E + ATT_E) att_out = y + OUT_E;

    cudaFuncSetAttribute(attn_kernel, cudaFuncAttributeMaxDynamicSharedMemorySize,
                         SMEM_ATTN);

    qkv16_kernel<<<BN * NN / 64, 256>>>(x, Wq, bq, Wk, bk, Wv, bv);
    attn_kernel<<<dim3(NN / 64, BN), 256, SMEM_ATTN>>>(x, gamma, att_out, y);
}